// round 1
// baseline (speedup 1.0000x reference)
#include <cuda_runtime.h>
#include <math.h>

// Problem constants (fixed by the dataset)
#define B_SZ 8
#define N_SZ 2048
#define F_SZ 128
#define ROWS_TOTAL (B_SZ * N_SZ)     // 16384
#define NEG_INF_V (-9.0e15f)
#define ALPHA 0.2f
#define LN_EPS 1e-5f

// Scratch (allocation-free rule: __device__ globals)
__device__ float g_h[ROWS_TOTAL * F_SZ];   // post-LN h (also the residual)
__device__ float g_s1[ROWS_TOTAL];
__device__ float g_s2[ROWS_TOTAL];

// ---------------------------------------------------------------------------
// Kernel 1: x' = x*(1+nw)+nb ; h = x'@W ; LayerNorm ; s1 = h.a1 ; s2 = h.a2
// 32 rows per CTA, 256 threads (8 warps x 4 rows), W staged in SMEM.
// ---------------------------------------------------------------------------
__global__ void __launch_bounds__(256) prep_kernel(
    const float* __restrict__ x, const float* __restrict__ W,
    const float* __restrict__ a, const float* __restrict__ nw,
    const float* __restrict__ nb, const float* __restrict__ gamma,
    const float* __restrict__ beta)
{
    extern __shared__ float sm[];
    float* Ws  = sm;               // 128*128 = 16384 floats
    float* xs  = sm + 16384;       // 32*128  = 4096 floats
    float* a1s = xs + 4096;        // 128
    float* a2s = a1s + 128;        // 128
    float* gs  = a2s + 128;        // 128
    float* bs  = gs + 128;         // 128

    const int tid  = threadIdx.x;
    const int row0 = blockIdx.x * 32;

#pragma unroll
    for (int k = 0; k < 64; k++) Ws[k * 256 + tid] = W[k * 256 + tid];
#pragma unroll
    for (int k = 0; k < 16; k++) {
        int idx = k * 256 + tid;
        int rl = idx >> 7, f = idx & 127;
        int row = row0 + rl;
        int n = row & (N_SZ - 1);
        xs[idx] = x[(size_t)row * F_SZ + f] * (1.0f + nw[n]) + nb[n];
    }
    if (tid < 128) {
        a1s[tid] = a[tid];
        a2s[tid] = a[128 + tid];
        gs[tid]  = gamma[tid];
        bs[tid]  = beta[tid];
    }
    __syncthreads();

    const int w = tid >> 5, lane = tid & 31;
    const int rbase = w * 4;

    float acc[4][4];
#pragma unroll
    for (int r = 0; r < 4; r++)
#pragma unroll
        for (int k = 0; k < 4; k++) acc[r][k] = 0.0f;

#pragma unroll 2
    for (int f = 0; f < 128; f++) {
        float w0 = Ws[f * 128 + lane];
        float w1 = Ws[f * 128 + 32 + lane];
        float w2 = Ws[f * 128 + 64 + lane];
        float w3 = Ws[f * 128 + 96 + lane];
#pragma unroll
        for (int r = 0; r < 4; r++) {
            float xv = xs[(rbase + r) * 128 + f];
            acc[r][0] += xv * w0;
            acc[r][1] += xv * w1;
            acc[r][2] += xv * w2;
            acc[r][3] += xv * w3;
        }
    }

#pragma unroll
    for (int r = 0; r < 4; r++) {
        int row = row0 + rbase + r;
        float s = acc[r][0] + acc[r][1] + acc[r][2] + acc[r][3];
#pragma unroll
        for (int o = 16; o; o >>= 1) s += __shfl_xor_sync(0xffffffffu, s, o);
        float mu = s * 0.0078125f;
        float d0 = acc[r][0] - mu, d1 = acc[r][1] - mu;
        float d2 = acc[r][2] - mu, d3 = acc[r][3] - mu;
        float v = d0 * d0 + d1 * d1 + d2 * d2 + d3 * d3;
#pragma unroll
        for (int o = 16; o; o >>= 1) v += __shfl_xor_sync(0xffffffffu, v, o);
        float rstd = rsqrtf(v * 0.0078125f + LN_EPS);
        float h0 = d0 * rstd * gs[lane]      + bs[lane];
        float h1 = d1 * rstd * gs[32 + lane] + bs[32 + lane];
        float h2 = d2 * rstd * gs[64 + lane] + bs[64 + lane];
        float h3 = d3 * rstd * gs[96 + lane] + bs[96 + lane];
        float s1p = h0 * a1s[lane] + h1 * a1s[32 + lane] + h2 * a1s[64 + lane] + h3 * a1s[96 + lane];
        float s2p = h0 * a2s[lane] + h1 * a2s[32 + lane] + h2 * a2s[64 + lane] + h3 * a2s[96 + lane];
#pragma unroll
        for (int o = 16; o; o >>= 1) {
            s1p += __shfl_xor_sync(0xffffffffu, s1p, o);
            s2p += __shfl_xor_sync(0xffffffffu, s2p, o);
        }
        size_t ro = (size_t)row * F_SZ;
        g_h[ro + lane]      = h0;
        g_h[ro + 32 + lane] = h1;
        g_h[ro + 64 + lane] = h2;
        g_h[ro + 96 + lane] = h3;
        if (lane == 0) { g_s1[row] = s1p; g_s2[row] = s2p; }
    }
}

// ---------------------------------------------------------------------------
// Kernel 2: flash-style masked softmax attention + A@h + residual + elu.
// Grid: (N/64, B). 256 threads. Group g = tid>>2 owns row i = blk*64+g;
// quad lane q = tid&3 owns 32 of the 128 output cols (float4 ids u*4+q).
// SMEM: h tile 128x128 f32 (64KB) + p buffer 64x132 f32 (33KB).
// ps layout: row g stride 132 floats, slot (jj*4 + q) for j = q*32+jj
//   -> writer banks (4g+4jj+q)%32 all distinct, reader float4 broadcast-clean.
// ---------------------------------------------------------------------------
__global__ void __launch_bounds__(256) attn_kernel(
    const int* __restrict__ adj, float* __restrict__ out)
{
    extern __shared__ float sm[];
    float*  hsf = sm;                 // 16384 floats
    float4* hs4 = (float4*)sm;        // 128 rows x 32 float4
    float*  ps  = sm + 16384;         // 64 * 132 floats

    const int tid = threadIdx.x;
    const int g = tid >> 2, q = tid & 3;
    const int b = blockIdx.y;
    const int i = blockIdx.x * 64 + g;

    const float* hb = g_h + (size_t)b * N_SZ * F_SZ;
    const float  s1v = g_s1[b * N_SZ + i];
    const float* s2b = g_s2 + b * N_SZ;
    const int*   adjrow = adj + (size_t)i * N_SZ;

    float4 acc[8];
#pragma unroll
    for (int u = 0; u < 8; u++) acc[u] = make_float4(0.f, 0.f, 0.f, 0.f);
    float m = -INFINITY, l = 0.0f;

    const int psbase = g * 132;

    for (int jt = 0; jt < N_SZ; jt += 128) {
        // --- stage h tile ---
        const float4* hsrc = (const float4*)(hb + (size_t)jt * F_SZ);
#pragma unroll
        for (int k = 0; k < 16; k++) hs4[k * 256 + tid] = hsrc[k * 256 + tid];
        __syncthreads();

        // --- pass 1: scores for this thread's 32 j's (j = q*32 + v*4 + c) ---
        float tmax = -INFINITY;
        const int4*   ap   = (const int4*)(adjrow + jt + q * 32);
        const float4* s2p4 = (const float4*)(s2b + jt + q * 32);
#pragma unroll
        for (int v = 0; v < 8; v++) {
            int4   a4 = ap[v];
            float4 s4 = s2p4[v];
            float e0 = s1v + s4.x, e1 = s1v + s4.y, e2 = s1v + s4.z, e3 = s1v + s4.w;
            float t0 = e0 > 0.f ? e0 : ALPHA * e0;
            float t1 = e1 > 0.f ? e1 : ALPHA * e1;
            float t2 = e2 > 0.f ? e2 : ALPHA * e2;
            float t3 = e3 > 0.f ? e3 : ALPHA * e3;
            t0 = a4.x > 0 ? t0 : NEG_INF_V;
            t1 = a4.y > 0 ? t1 : NEG_INF_V;
            t2 = a4.z > 0 ? t2 : NEG_INF_V;
            t3 = a4.w > 0 ? t3 : NEG_INF_V;
            ps[psbase + (v * 4 + 0) * 4 + q] = t0;
            ps[psbase + (v * 4 + 1) * 4 + q] = t1;
            ps[psbase + (v * 4 + 2) * 4 + q] = t2;
            ps[psbase + (v * 4 + 3) * 4 + q] = t3;
            tmax = fmaxf(tmax, fmaxf(fmaxf(t0, t1), fmaxf(t2, t3)));
        }
        tmax = fmaxf(tmax, __shfl_xor_sync(0xffffffffu, tmax, 1));
        tmax = fmaxf(tmax, __shfl_xor_sync(0xffffffffu, tmax, 2));

        float mn = fmaxf(m, tmax);
        float scale = __expf(m - mn);   // exp(-inf)=0 handles first tile
        l *= scale;
#pragma unroll
        for (int u = 0; u < 8; u++) {
            acc[u].x *= scale; acc[u].y *= scale;
            acc[u].z *= scale; acc[u].w *= scale;
        }
        float lsum = 0.0f;
#pragma unroll
        for (int jj = 0; jj < 32; jj++) {
            int idx = psbase + jj * 4 + q;
            float p = __expf(ps[idx] - mn);
            ps[idx] = p;
            lsum += p;
        }
        lsum += __shfl_xor_sync(0xffffffffu, lsum, 1);
        lsum += __shfl_xor_sync(0xffffffffu, lsum, 2);
        l += lsum;
        m = mn;
        __syncwarp();   // quad cross-lane ps visibility (all within one warp)

        // --- pass 2: acc += p_j * h[j, cols(q)] ---
#pragma unroll 2
        for (int jj = 0; jj < 32; jj++) {
            float4 p4 = *(const float4*)&ps[psbase + jj * 4];
            float pv[4] = {p4.x, p4.y, p4.z, p4.w};
#pragma unroll
            for (int qq = 0; qq < 4; qq++) {
                float p = pv[qq];
                const float4* hr = hs4 + (qq * 32 + jj) * 32;
#pragma unroll
                for (int u = 0; u < 8; u++) {
                    float4 hv = hr[u * 4 + q];
                    acc[u].x += p * hv.x;
                    acc[u].y += p * hv.y;
                    acc[u].z += p * hv.z;
                    acc[u].w += p * hv.w;
                }
            }
        }
        __syncthreads();   // hs (and ps) reuse barrier before next tile
    }

    // --- epilogue: normalize, +residual, elu ---
    float invl = 1.0f / l;
    const float4* res  = (const float4*)(hb + (size_t)i * F_SZ);
    float4*       orow = (float4*)(out + ((size_t)b * N_SZ + i) * F_SZ);
#pragma unroll
    for (int u = 0; u < 8; u++) {
        int c4 = u * 4 + q;
        float4 r = res[c4];
        float4 o;
        o.x = acc[u].x * invl + r.x;
        o.y = acc[u].y * invl + r.y;
        o.z = acc[u].z * invl + r.z;
        o.w = acc[u].w * invl + r.w;
        o.x = o.x > 0.f ? o.x : __expf(o.x) - 1.0f;
        o.y = o.y > 0.f ? o.y : __expf(o.y) - 1.0f;
        o.z = o.z > 0.f ? o.z : __expf(o.z) - 1.0f;
        o.w = o.w > 0.f ? o.w : __expf(o.w) - 1.0f;
        orow[c4] = o;
    }
}

// ---------------------------------------------------------------------------
extern "C" void kernel_launch(void* const* d_in, const int* in_sizes, int n_in,
                              void* d_out, int out_size)
{
    const float* x     = (const float*)d_in[0];
    const int*   adj   = (const int*)d_in[1];
    const float* W     = (const float*)d_in[2];
    const float* a     = (const float*)d_in[3];
    const float* nw    = (const float*)d_in[4];
    const float* nb    = (const float*)d_in[5];
    const float* gamma = (const float*)d_in[6];
    const float* beta  = (const float*)d_in[7];
    float* out = (float*)d_out;

    const int prep_smem = (16384 + 4096 + 4 * 128) * 4;   // 83968 B
    const int attn_smem = (16384 + 64 * 132) * 4;          // 99328 B
    cudaFuncSetAttribute(prep_kernel, cudaFuncAttributeMaxDynamicSharedMemorySize, prep_smem);
    cudaFuncSetAttribute(attn_kernel, cudaFuncAttributeMaxDynamicSharedMemorySize, attn_smem);

    prep_kernel<<<ROWS_TOTAL / 32, 256, prep_smem>>>(x, W, a, nw, nb, gamma, beta);

    dim3 grid(N_SZ / 64, B_SZ);
    attn_kernel<<<grid, 256, attn_smem>>>(adj, out);
}

// round 2
// speedup vs baseline: 3.7341x; 3.7341x over previous
#include <cuda_runtime.h>
#include <math.h>

#define B_SZ 8
#define N_SZ 2048
#define F_SZ 128
#define ROWS_TOTAL (B_SZ * N_SZ)
#define ALPHA 0.2f
#define LN_EPS 1e-5f

// Scratch
__device__ float g_h[ROWS_TOTAL * F_SZ];   // post-LN h (also the residual)
__device__ float g_s1[ROWS_TOTAL];
__device__ float g_s2[ROWS_TOTAL];

__device__ __forceinline__ unsigned f2tf(float f) {
    unsigned u;
    asm("cvt.rna.tf32.f32 %0, %1;" : "=r"(u) : "f"(f));
    return u;
}

// ---------------------------------------------------------------------------
// Kernel 1: x' = x*(1+nw)+nb ; h = x'@W ; LayerNorm ; s1 = h.a1 ; s2 = h.a2
// (unchanged from R1 — ~15 us)
// ---------------------------------------------------------------------------
__global__ void __launch_bounds__(256) prep_kernel(
    const float* __restrict__ x, const float* __restrict__ W,
    const float* __restrict__ a, const float* __restrict__ nw,
    const float* __restrict__ nb, const float* __restrict__ gamma,
    const float* __restrict__ beta)
{
    extern __shared__ float sm[];
    float* Ws  = sm;
    float* xs  = sm + 16384;
    float* a1s = xs + 4096;
    float* a2s = a1s + 128;
    float* gs  = a2s + 128;
    float* bs  = gs + 128;

    const int tid  = threadIdx.x;
    const int row0 = blockIdx.x * 32;

#pragma unroll
    for (int k = 0; k < 64; k++) Ws[k * 256 + tid] = W[k * 256 + tid];
#pragma unroll
    for (int k = 0; k < 16; k++) {
        int idx = k * 256 + tid;
        int rl = idx >> 7, f = idx & 127;
        int row = row0 + rl;
        int n = row & (N_SZ - 1);
        xs[idx] = x[(size_t)row * F_SZ + f] * (1.0f + nw[n]) + nb[n];
    }
    if (tid < 128) {
        a1s[tid] = a[tid];
        a2s[tid] = a[128 + tid];
        gs[tid]  = gamma[tid];
        bs[tid]  = beta[tid];
    }
    __syncthreads();

    const int w = tid >> 5, lane = tid & 31;
    const int rbase = w * 4;

    float acc[4][4];
#pragma unroll
    for (int r = 0; r < 4; r++)
#pragma unroll
        for (int k = 0; k < 4; k++) acc[r][k] = 0.0f;

#pragma unroll 2
    for (int f = 0; f < 128; f++) {
        float w0 = Ws[f * 128 + lane];
        float w1 = Ws[f * 128 + 32 + lane];
        float w2 = Ws[f * 128 + 64 + lane];
        float w3 = Ws[f * 128 + 96 + lane];
#pragma unroll
        for (int r = 0; r < 4; r++) {
            float xv = xs[(rbase + r) * 128 + f];
            acc[r][0] += xv * w0;
            acc[r][1] += xv * w1;
            acc[r][2] += xv * w2;
            acc[r][3] += xv * w3;
        }
    }

#pragma unroll
    for (int r = 0; r < 4; r++) {
        int row = row0 + rbase + r;
        float s = acc[r][0] + acc[r][1] + acc[r][2] + acc[r][3];
#pragma unroll
        for (int o = 16; o; o >>= 1) s += __shfl_xor_sync(0xffffffffu, s, o);
        float mu = s * 0.0078125f;
        float d0 = acc[r][0] - mu, d1 = acc[r][1] - mu;
        float d2 = acc[r][2] - mu, d3 = acc[r][3] - mu;
        float v = d0 * d0 + d1 * d1 + d2 * d2 + d3 * d3;
#pragma unroll
        for (int o = 16; o; o >>= 1) v += __shfl_xor_sync(0xffffffffu, v, o);
        float rstd = rsqrtf(v * 0.0078125f + LN_EPS);
        float h0 = d0 * rstd * gs[lane]      + bs[lane];
        float h1 = d1 * rstd * gs[32 + lane] + bs[32 + lane];
        float h2 = d2 * rstd * gs[64 + lane] + bs[64 + lane];
        float h3 = d3 * rstd * gs[96 + lane] + bs[96 + lane];
        float s1p = h0 * a1s[lane] + h1 * a1s[32 + lane] + h2 * a1s[64 + lane] + h3 * a1s[96 + lane];
        float s2p = h0 * a2s[lane] + h1 * a2s[32 + lane] + h2 * a2s[64 + lane] + h3 * a2s[96 + lane];
#pragma unroll
        for (int o = 16; o; o >>= 1) {
            s1p += __shfl_xor_sync(0xffffffffu, s1p, o);
            s2p += __shfl_xor_sync(0xffffffffu, s2p, o);
        }
        size_t ro = (size_t)row * F_SZ;
        g_h[ro + lane]      = h0;
        g_h[ro + 32 + lane] = h1;
        g_h[ro + 64 + lane] = h2;
        g_h[ro + 96 + lane] = h3;
        if (lane == 0) { g_s1[row] = s1p; g_s2[row] = s2p; }
    }
}

// ---------------------------------------------------------------------------
// Kernel 2: masked-softmax attention via tf32 mma.sync, no online rescale.
//   Scores bounded (|s1+s2| < ~10) -> exp without max-subtract is exact
//   relative to the reference softmax (shift invariance).
// CTA: 64 i-rows, 256 threads (8 warps). Warp w: i-block (w&1)*32 (2 igroups
// of m16), f-block (w>>1)*32 (4 n-tiles of n8). k-steps of 8 over j-tile 128.
// SMEM (104,192 B -> 2 CTA/SM):
//   Hs[128][136] tf32  — B operand, bank(8t+g) conflict-free
//   Ps[64][132]  tf32  — A operand, bank(4g+t) conflict-free; pass-1 writes
//                        with j=4*jj+q -> bank(4g+4jj+q) conflict-free
//   s2s[128], l_s[64]
// ---------------------------------------------------------------------------
__global__ void __launch_bounds__(256, 2) attn_kernel(
    const int* __restrict__ adj, float* __restrict__ out)
{
    extern __shared__ char smc[];
    unsigned* Hs = (unsigned*)smc;                       // 128*136 = 17408 words
    unsigned* Ps = (unsigned*)(smc + 69632);             // 64*132  =  8448 words
    float*   s2s = (float*)(smc + 69632 + 33792);        // 128
    float*   l_s = s2s + 128;                            // 64

    const int tid  = threadIdx.x;
    const int w    = tid >> 5;
    const int lane = tid & 31;
    const int g    = lane >> 2;     // 0..7
    const int t    = lane & 3;      // 0..3
    const int b    = blockIdx.y;
    const int i0   = blockIdx.x * 64;          // CTA row base

    // pass-1 identity: row G (0..63), quad lane q
    const int G = tid >> 2;
    const int q = tid & 3;
    const float s1v = g_s1[b * N_SZ + i0 + G];
    const long  adjbase = (long)(i0 + G) * N_SZ;

    // mma identity
    const int ib = (w & 1) * 32;     // local i-block
    const int fb = (w >> 1) * 32;    // f-block

    const float* hb = g_h + (size_t)b * N_SZ * F_SZ;

    float acc[2][4][4];
#pragma unroll
    for (int ig = 0; ig < 2; ig++)
#pragma unroll
        for (int n = 0; n < 4; n++)
#pragma unroll
            for (int r = 0; r < 4; r++) acc[ig][n][r] = 0.0f;
    float lacc = 0.0f;

    for (int jt = 0; jt < N_SZ; jt += 128) {
        __syncthreads();   // previous tile's mma reads done

        // ---- stage H tile (fp32 -> tf32) ----
        {
            const float4* src = (const float4*)(hb + (size_t)jt * F_SZ);
#pragma unroll
            for (int kk = 0; kk < 16; kk++) {
                int idx = kk * 256 + tid;
                float4 v = src[idx];
                int row = idx >> 5, c4 = idx & 31;
                unsigned* dst = Hs + row * 136 + c4 * 4;
                dst[0] = f2tf(v.x); dst[1] = f2tf(v.y);
                dst[2] = f2tf(v.z); dst[3] = f2tf(v.w);
            }
            if (tid < 128) s2s[tid] = g_s2[b * N_SZ + jt + tid];
        }
        __syncthreads();

        // ---- pass 1: p = adj>0 ? exp(lrelu(s1+s2)) : 0  (tf32) ----
#pragma unroll 4
        for (int jj = 0; jj < 32; jj++) {
            int jl = 4 * jj + q;
            int av = __ldg(adj + adjbase + jt + jl);
            float e = s1v + s2s[jl];
            float tt = e > 0.0f ? e : ALPHA * e;
            float p = av > 0 ? __expf(tt) : 0.0f;
            unsigned pt = f2tf(p);
            Ps[G * 132 + jl] = pt;
            lacc += __uint_as_float(pt);
        }
        __syncthreads();

        // ---- mma: ACC[64x128] += P[64x128] @ H[128x128] ----
#pragma unroll 4
        for (int k = 0; k < 16; k++) {
            unsigned a0[2], a1[2], a2[2], a3[2];
#pragma unroll
            for (int ig = 0; ig < 2; ig++) {
                const unsigned* pr = Ps + (ib + ig * 16 + g) * 132 + k * 8 + t;
                a0[ig] = pr[0];
                a2[ig] = pr[4];
                const unsigned* pr8 = pr + 8 * 132;
                a1[ig] = pr8[0];
                a3[ig] = pr8[4];
            }
            unsigned b0[4], b1[4];
#pragma unroll
            for (int n = 0; n < 4; n++) {
                const unsigned* hr = Hs + (k * 8 + t) * 136 + fb + n * 8 + g;
                b0[n] = hr[0];
                b1[n] = hr[4 * 136];
            }
#pragma unroll
            for (int ig = 0; ig < 2; ig++)
#pragma unroll
                for (int n = 0; n < 4; n++) {
                    asm volatile(
                        "mma.sync.aligned.m16n8k8.row.col.f32.tf32.tf32.f32 "
                        "{%0,%1,%2,%3}, {%4,%5,%6,%7}, {%8,%9}, {%0,%1,%2,%3};"
                        : "+f"(acc[ig][n][0]), "+f"(acc[ig][n][1]),
                          "+f"(acc[ig][n][2]), "+f"(acc[ig][n][3])
                        : "r"(a0[ig]), "r"(a1[ig]), "r"(a2[ig]), "r"(a3[ig]),
                          "r"(b0[n]), "r"(b1[n]));
                }
        }
    }

    // ---- row sums l ----
    lacc += __shfl_xor_sync(0xffffffffu, lacc, 1);
    lacc += __shfl_xor_sync(0xffffffffu, lacc, 2);
    if (q == 0) l_s[G] = lacc;
    __syncthreads();

    // ---- epilogue: normalize, +residual, elu, store ----
#pragma unroll
    for (int ig = 0; ig < 2; ig++) {
#pragma unroll
        for (int rp = 0; rp < 2; rp++) {
            int rl = ib + ig * 16 + g + 8 * rp;
            float invl = 1.0f / l_s[rl];
            int i = i0 + rl;
#pragma unroll
            for (int n = 0; n < 4; n++) {
                int col = fb + n * 8 + t * 2;
                const float2 r = *(const float2*)(hb + (size_t)i * F_SZ + col);
                float ox = acc[ig][n][2 * rp]     * invl + r.x;
                float oy = acc[ig][n][2 * rp + 1] * invl + r.y;
                ox = ox > 0.0f ? ox : __expf(ox) - 1.0f;
                oy = oy > 0.0f ? oy : __expf(oy) - 1.0f;
                float2 o = make_float2(ox, oy);
                *(float2*)(out + ((size_t)b * N_SZ + i) * F_SZ + col) = o;
            }
        }
    }
}

// ---------------------------------------------------------------------------
extern "C" void kernel_launch(void* const* d_in, const int* in_sizes, int n_in,
                              void* d_out, int out_size)
{
    const float* x     = (const float*)d_in[0];
    const int*   adj   = (const int*)d_in[1];
    const float* W     = (const float*)d_in[2];
    const float* a     = (const float*)d_in[3];
    const float* nw    = (const float*)d_in[4];
    const float* nb    = (const float*)d_in[5];
    const float* gamma = (const float*)d_in[6];
    const float* beta  = (const float*)d_in[7];
    float* out = (float*)d_out;

    const int prep_smem = (16384 + 4096 + 4 * 128) * 4;         // 83968 B
    const int attn_smem = 69632 + 33792 + 512 + 256;            // 104192 B
    cudaFuncSetAttribute(prep_kernel, cudaFuncAttributeMaxDynamicSharedMemorySize, prep_smem);
    cudaFuncSetAttribute(attn_kernel, cudaFuncAttributeMaxDynamicSharedMemorySize, attn_smem);

    prep_kernel<<<ROWS_TOTAL / 32, 256, prep_smem>>>(x, W, a, nw, nb, gamma, beta);

    dim3 grid(N_SZ / 64, B_SZ);
    attn_kernel<<<grid, 256, attn_smem>>>(adj, out);
}

// round 3
// speedup vs baseline: 6.8508x; 1.8347x over previous
#include <cuda_runtime.h>
#include <cuda_bf16.h>
#include <math.h>

#define B_SZ 8
#define N_SZ 2048
#define F_SZ 128
#define ROWS_TOTAL (B_SZ * N_SZ)
#define ALPHA 0.2f
#define LN_EPS 1e-5f

// Scratch (__device__ globals: allocation-free rule)
__device__ float          g_h [ROWS_TOTAL * F_SZ];   // post-LN h fp32 (residual/epilogue)
__device__ __nv_bfloat16  g_hb[ROWS_TOTAL * F_SZ];   // post-LN h bf16 (mma operand)
__device__ float          g_s1[ROWS_TOTAL];
__device__ float          g_s2[ROWS_TOTAL];
__device__ unsigned       g_adjbits[N_SZ * (N_SZ / 32)];  // row-major bitmask

// ---------------------------------------------------------------------------
// Kernel 0: pack adj (int32 0/1) into bitmask via warp ballot.
// ---------------------------------------------------------------------------
__global__ void __launch_bounds__(256) pack_kernel(const int* __restrict__ adj)
{
    int gid = blockIdx.x * 256 + threadIdx.x;
    int av = adj[gid];
    unsigned w = __ballot_sync(0xffffffffu, av > 0);
    if ((threadIdx.x & 31) == 0) g_adjbits[gid >> 5] = w;
}

// ---------------------------------------------------------------------------
// Kernel 1: x' = x*(1+nw)+nb ; h = x'@W ; LayerNorm ; s1/s2 ; emit fp32+bf16.
// ---------------------------------------------------------------------------
__global__ void __launch_bounds__(256) prep_kernel(
    const float* __restrict__ x, const float* __restrict__ W,
    const float* __restrict__ a, const float* __restrict__ nw,
    const float* __restrict__ nb, const float* __restrict__ gamma,
    const float* __restrict__ beta)
{
    extern __shared__ float sm[];
    float* Ws  = sm;
    float* xs  = sm + 16384;
    float* a1s = xs + 4096;
    float* a2s = a1s + 128;
    float* gs  = a2s + 128;
    float* bs  = gs + 128;

    const int tid  = threadIdx.x;
    const int row0 = blockIdx.x * 32;

#pragma unroll
    for (int k = 0; k < 64; k++) Ws[k * 256 + tid] = W[k * 256 + tid];
#pragma unroll
    for (int k = 0; k < 16; k++) {
        int idx = k * 256 + tid;
        int rl = idx >> 7, f = idx & 127;
        int row = row0 + rl;
        int n = row & (N_SZ - 1);
        xs[idx] = x[(size_t)row * F_SZ + f] * (1.0f + nw[n]) + nb[n];
    }
    if (tid < 128) {
        a1s[tid] = a[tid];
        a2s[tid] = a[128 + tid];
        gs[tid]  = gamma[tid];
        bs[tid]  = beta[tid];
    }
    __syncthreads();

    const int w = tid >> 5, lane = tid & 31;
    const int rbase = w * 4;

    float acc[4][4];
#pragma unroll
    for (int r = 0; r < 4; r++)
#pragma unroll
        for (int k = 0; k < 4; k++) acc[r][k] = 0.0f;

#pragma unroll 2
    for (int f = 0; f < 128; f++) {
        float w0 = Ws[f * 128 + lane];
        float w1 = Ws[f * 128 + 32 + lane];
        float w2 = Ws[f * 128 + 64 + lane];
        float w3 = Ws[f * 128 + 96 + lane];
#pragma unroll
        for (int r = 0; r < 4; r++) {
            float xv = xs[(rbase + r) * 128 + f];
            acc[r][0] += xv * w0;
            acc[r][1] += xv * w1;
            acc[r][2] += xv * w2;
            acc[r][3] += xv * w3;
        }
    }

#pragma unroll
    for (int r = 0; r < 4; r++) {
        int row = row0 + rbase + r;
        float s = acc[r][0] + acc[r][1] + acc[r][2] + acc[r][3];
#pragma unroll
        for (int o = 16; o; o >>= 1) s += __shfl_xor_sync(0xffffffffu, s, o);
        float mu = s * 0.0078125f;
        float d0 = acc[r][0] - mu, d1 = acc[r][1] - mu;
        float d2 = acc[r][2] - mu, d3 = acc[r][3] - mu;
        float v = d0 * d0 + d1 * d1 + d2 * d2 + d3 * d3;
#pragma unroll
        for (int o = 16; o; o >>= 1) v += __shfl_xor_sync(0xffffffffu, v, o);
        float rstd = rsqrtf(v * 0.0078125f + LN_EPS);
        float h0 = d0 * rstd * gs[lane]      + bs[lane];
        float h1 = d1 * rstd * gs[32 + lane] + bs[32 + lane];
        float h2 = d2 * rstd * gs[64 + lane] + bs[64 + lane];
        float h3 = d3 * rstd * gs[96 + lane] + bs[96 + lane];
        float s1p = h0 * a1s[lane] + h1 * a1s[32 + lane] + h2 * a1s[64 + lane] + h3 * a1s[96 + lane];
        float s2p = h0 * a2s[lane] + h1 * a2s[32 + lane] + h2 * a2s[64 + lane] + h3 * a2s[96 + lane];
#pragma unroll
        for (int o = 16; o; o >>= 1) {
            s1p += __shfl_xor_sync(0xffffffffu, s1p, o);
            s2p += __shfl_xor_sync(0xffffffffu, s2p, o);
        }
        size_t ro = (size_t)row * F_SZ;
        g_h[ro + lane]      = h0;
        g_h[ro + 32 + lane] = h1;
        g_h[ro + 64 + lane] = h2;
        g_h[ro + 96 + lane] = h3;
        g_hb[ro + lane]      = __float2bfloat16(h0);
        g_hb[ro + 32 + lane] = __float2bfloat16(h1);
        g_hb[ro + 64 + lane] = __float2bfloat16(h2);
        g_hb[ro + 96 + lane] = __float2bfloat16(h3);
        if (lane == 0) { g_s1[row] = s1p; g_s2[row] = s2p; }
    }
}

// ---------------------------------------------------------------------------
// Kernel 2: attention via bf16 mma.m16n8k16 + ldmatrix, double-buffered
// cp.async H staging, bitmask adj, no online softmax (scores bounded).
// CTA: 64 i-rows x 128 f, 256 thr (8 warps: warp w -> i-block (w&1)*32,
// f-block (w>>2... (w>>1)*32). SMEM: Hs[2][128][136]bf16 + Ps[64][136]bf16.
// ---------------------------------------------------------------------------
__global__ void __launch_bounds__(256, 2) attn_kernel(float* __restrict__ out)
{
    extern __shared__ char smc[];
    // Hs buffers: 128 rows * 136 bf16 (272 B row stride) each
    const unsigned HS_BYTES = 128 * 272;         // 34816
    __nv_bfloat16* HsGen = (__nv_bfloat16*)smc;  // generic ptr base
    unsigned* Ps32 = (unsigned*)(smc + 2 * HS_BYTES);        // 64 * 68 words
    float*    l_s  = (float*)(smc + 2 * HS_BYTES + 64 * 272);

    const unsigned smemBase = (unsigned)__cvta_generic_to_shared(smc);
    const unsigned psBase   = smemBase + 2 * HS_BYTES;

    const int tid  = threadIdx.x;
    const int w    = tid >> 5;
    const int lane = tid & 31;
    const int b    = blockIdx.y;
    const int i0   = blockIdx.x * 64;

    // pass-1 identity
    const int G = tid >> 2, q = tid & 3;
    const float s1v = g_s1[b * N_SZ + i0 + G];
    const uint4* bits4 = (const uint4*)g_adjbits + (size_t)(i0 + G) * 16;
    const float* s2b = g_s2 + b * N_SZ;

    // mma identity
    const int ib = (w & 1) * 32;
    const int fb = (w >> 1) * 32;

    const __nv_bfloat16* hbb = g_hb + (size_t)b * N_SZ * F_SZ;
    const float*         hbf = g_h  + (size_t)b * N_SZ * F_SZ;

    // ldmatrix lane addresses (byte offsets within buffers)
    // A (Ps): row = ib + ig*16 + (lane&15); col byte = (lane>>4)*16 (+k0*2)
    const unsigned aOff0 = psBase + (unsigned)(ib + (lane & 15)) * 272 + (unsigned)(lane >> 4) * 16;
    const unsigned aOff1 = aOff0 + 16 * 272;
    // B (Hs): k-row = (lane&15) (+k0); n = fb + pair*16 + (lane>>4)*8
    const unsigned bRow = (unsigned)(lane & 15) * 272;
    const unsigned bCol0 = (unsigned)(fb + ((lane >> 4) * 8)) * 2;
    const unsigned bCol1 = bCol0 + 32;   // +16 cols * 2B

    float acc[2][4][4];
#pragma unroll
    for (int ig = 0; ig < 2; ig++)
#pragma unroll
        for (int n = 0; n < 4; n++)
#pragma unroll
            for (int r = 0; r < 4; r++) acc[ig][n][r] = 0.0f;
    float lacc = 0.0f;

    // ---- prologue: stage tile 0 into buf 0 ----
    {
        const char* src = (const char*)(hbb);
#pragma unroll
        for (int kk = 0; kk < 8; kk++) {
            int idx = kk * 256 + tid;
            int row = idx >> 4, c16 = idx & 15;
            unsigned dst = smemBase + (unsigned)row * 272 + (unsigned)c16 * 16;
            asm volatile("cp.async.cg.shared.global [%0], [%1], 16;\n"
                         :: "r"(dst), "l"(src + row * 256 + c16 * 16));
        }
        asm volatile("cp.async.commit_group;\n");
    }

    for (int T = 0; T < 16; T++) {
        const int jt = T * 128;

        // ---- issue stage of next tile into other buffer ----
        if (T < 15) {
            const char* src = (const char*)(hbb + (size_t)(jt + 128) * F_SZ);
            unsigned dbase = smemBase + (unsigned)(((T + 1) & 1)) * HS_BYTES;
#pragma unroll
            for (int kk = 0; kk < 8; kk++) {
                int idx = kk * 256 + tid;
                int row = idx >> 4, c16 = idx & 15;
                unsigned dst = dbase + (unsigned)row * 272 + (unsigned)c16 * 16;
                asm volatile("cp.async.cg.shared.global [%0], [%1], 16;\n"
                             :: "r"(dst), "l"(src + row * 256 + c16 * 16));
            }
            asm volatile("cp.async.commit_group;\n");
        }

        // ---- pass 1: p = bit ? exp(lrelu(s1+s2)) : 0, packed bf16x2 ----
        {
            uint4 m = bits4[T];
            unsigned mw[4] = {m.x, m.y, m.z, m.w};
            unsigned* psrow = Ps32 + G * 68;
#pragma unroll
            for (int w4 = 0; w4 < 4; w4++) {
                unsigned mm = mw[w4];
#pragma unroll
                for (int u = 0; u < 4; u++) {
                    int jj = w4 * 4 + u;
                    int j0 = 8 * jj + 2 * q;
                    float2 s2v = *(const float2*)(s2b + jt + j0);
                    float e0 = s1v + s2v.x, e1 = s1v + s2v.y;
                    float t0 = e0 > 0.f ? e0 : ALPHA * e0;
                    float t1 = e1 > 0.f ? e1 : ALPHA * e1;
                    unsigned bits = (mm >> (8 * u + 2 * q)) & 3u;
                    float p0 = (bits & 1u) ? __expf(t0) : 0.0f;
                    float p1 = (bits & 2u) ? __expf(t1) : 0.0f;
                    __nv_bfloat162 pp = __floats2bfloat162_rn(p0, p1);
                    psrow[4 * jj + q] = *(unsigned*)&pp;
                    float2 pf = __bfloat1622float2(pp);
                    lacc += pf.x + pf.y;
                }
            }
        }

        // ---- wait staging of current tile, make Ps visible ----
        if (T < 15) asm volatile("cp.async.wait_group 1;\n");
        else        asm volatile("cp.async.wait_group 0;\n");
        __syncthreads();

        // ---- mma: ACC += P[64x128] @ H[128x128] ----
        const unsigned hsB = smemBase + (unsigned)(T & 1) * HS_BYTES;
#pragma unroll
        for (int k = 0; k < 8; k++) {      // k0 = k*16
            unsigned a0[2][4];
            {
                unsigned addr = aOff0 + k * 32;
                asm volatile("ldmatrix.sync.aligned.m8n8.x4.shared.b16 {%0,%1,%2,%3}, [%4];"
                             : "=r"(a0[0][0]), "=r"(a0[0][1]), "=r"(a0[0][2]), "=r"(a0[0][3])
                             : "r"(addr));
                addr = aOff1 + k * 32;
                asm volatile("ldmatrix.sync.aligned.m8n8.x4.shared.b16 {%0,%1,%2,%3}, [%4];"
                             : "=r"(a0[1][0]), "=r"(a0[1][1]), "=r"(a0[1][2]), "=r"(a0[1][3])
                             : "r"(addr));
            }
            unsigned bb[2][4];
            {
                unsigned addr = hsB + bRow + (unsigned)k * 16 * 272 + bCol0;
                asm volatile("ldmatrix.sync.aligned.m8n8.x4.trans.shared.b16 {%0,%1,%2,%3}, [%4];"
                             : "=r"(bb[0][0]), "=r"(bb[0][1]), "=r"(bb[0][2]), "=r"(bb[0][3])
                             : "r"(addr));
                addr = hsB + bRow + (unsigned)k * 16 * 272 + bCol1;
                asm volatile("ldmatrix.sync.aligned.m8n8.x4.trans.shared.b16 {%0,%1,%2,%3}, [%4];"
                             : "=r"(bb[1][0]), "=r"(bb[1][1]), "=r"(bb[1][2]), "=r"(bb[1][3])
                             : "r"(addr));
            }
#pragma unroll
            for (int ig = 0; ig < 2; ig++) {
#pragma unroll
                for (int n = 0; n < 4; n++) {
                    // ntile n: pair = n>>1, half = n&1 -> regs bb[pair][2*half..]
                    asm volatile(
                        "mma.sync.aligned.m16n8k16.row.col.f32.bf16.bf16.f32 "
                        "{%0,%1,%2,%3}, {%4,%5,%6,%7}, {%8,%9}, {%0,%1,%2,%3};"
                        : "+f"(acc[ig][n][0]), "+f"(acc[ig][n][1]),
                          "+f"(acc[ig][n][2]), "+f"(acc[ig][n][3])
                        : "r"(a0[ig][0]), "r"(a0[ig][1]), "r"(a0[ig][2]), "r"(a0[ig][3]),
                          "r"(bb[n >> 1][2 * (n & 1)]), "r"(bb[n >> 1][2 * (n & 1) + 1]));
                }
            }
        }
        __syncthreads();   // mma done reading Ps/Hs before overwrite
    }

    // ---- row sums ----
    lacc += __shfl_xor_sync(0xffffffffu, lacc, 1);
    lacc += __shfl_xor_sync(0xffffffffu, lacc, 2);
    if (q == 0) l_s[G] = lacc;
    __syncthreads();

    // ---- epilogue: normalize, +residual, elu ----
#pragma unroll
    for (int ig = 0; ig < 2; ig++) {
#pragma unroll
        for (int rp = 0; rp < 2; rp++) {
            int rl = ib + ig * 16 + (lane >> 2) + 8 * rp;
            float invl = 1.0f / l_s[rl];
            int i = i0 + rl;
#pragma unroll
            for (int n = 0; n < 4; n++) {
                int col = fb + n * 8 + (lane & 3) * 2;
                const float2 r = *(const float2*)(hbf + (size_t)i * F_SZ + col);
                float ox = acc[ig][n][2 * rp]     * invl + r.x;
                float oy = acc[ig][n][2 * rp + 1] * invl + r.y;
                ox = ox > 0.0f ? ox : __expf(ox) - 1.0f;
                oy = oy > 0.0f ? oy : __expf(oy) - 1.0f;
                *(float2*)(out + ((size_t)b * N_SZ + i) * F_SZ + col) = make_float2(ox, oy);
            }
        }
    }
}

// ---------------------------------------------------------------------------
extern "C" void kernel_launch(void* const* d_in, const int* in_sizes, int n_in,
                              void* d_out, int out_size)
{
    const float* x     = (const float*)d_in[0];
    const int*   adj   = (const int*)d_in[1];
    const float* W     = (const float*)d_in[2];
    const float* a     = (const float*)d_in[3];
    const float* nw    = (const float*)d_in[4];
    const float* nb    = (const float*)d_in[5];
    const float* gamma = (const float*)d_in[6];
    const float* beta  = (const float*)d_in[7];
    float* out = (float*)d_out;

    const int prep_smem = (16384 + 4096 + 4 * 128) * 4;        // 83968 B
    const int attn_smem = 2 * 34816 + 64 * 272 + 256;          // 87296 B
    cudaFuncSetAttribute(prep_kernel, cudaFuncAttributeMaxDynamicSharedMemorySize, prep_smem);
    cudaFuncSetAttribute(attn_kernel, cudaFuncAttributeMaxDynamicSharedMemorySize, attn_smem);

    pack_kernel<<<(N_SZ * N_SZ) / 256, 256>>>(adj);
    prep_kernel<<<ROWS_TOTAL / 32, 256, prep_smem>>>(x, W, a, nw, nb, gamma, beta);

    dim3 grid(N_SZ / 64, B_SZ);
    attn_kernel<<<grid, 256, attn_smem>>>(out);
}

// round 4
// speedup vs baseline: 6.8894x; 1.0056x over previous
#include <cuda_runtime.h>
#include <cuda_bf16.h>
#include <math.h>

#define B_SZ 8
#define N_SZ 2048
#define F_SZ 128
#define ROWS_TOTAL (B_SZ * N_SZ)
#define ALPHA 0.2f
#define LN_EPS 1e-5f

// Scratch (__device__ globals: allocation-free rule)
__device__ float          g_h [ROWS_TOTAL * F_SZ];   // post-LN h fp32 (residual/epilogue)
__device__ __nv_bfloat16  g_hb[ROWS_TOTAL * F_SZ];   // post-LN h bf16 (mma operand)
__device__ float          g_s1[ROWS_TOTAL];
__device__ float          g_s2[ROWS_TOTAL];
__device__ unsigned       g_adjbits[N_SZ * (N_SZ / 32)];  // row-major bitmask

// ---------------------------------------------------------------------------
// Kernel 0: pack adj (int32 0/1) into bitmask via warp ballot.
// ---------------------------------------------------------------------------
__global__ void __launch_bounds__(256) pack_kernel(const int* __restrict__ adj)
{
    int gid = blockIdx.x * 256 + threadIdx.x;
    int av = adj[gid];
    unsigned w = __ballot_sync(0xffffffffu, av > 0);
    if ((threadIdx.x & 31) == 0) g_adjbits[gid >> 5] = w;
}

// ---------------------------------------------------------------------------
// Kernel 1: x' = x*(1+nw)+nb ; h = x'@W ; LayerNorm ; s1/s2 ; emit fp32+bf16.
// ---------------------------------------------------------------------------
__global__ void __launch_bounds__(256) prep_kernel(
    const float* __restrict__ x, const float* __restrict__ W,
    const float* __restrict__ a, const float* __restrict__ nw,
    const float* __restrict__ nb, const float* __restrict__ gamma,
    const float* __restrict__ beta)
{
    extern __shared__ float sm[];
    float* Ws  = sm;
    float* xs  = sm + 16384;
    float* a1s = xs + 4096;
    float* a2s = a1s + 128;
    float* gs  = a2s + 128;
    float* bs  = gs + 128;

    const int tid  = threadIdx.x;
    const int row0 = blockIdx.x * 32;

#pragma unroll
    for (int k = 0; k < 64; k++) Ws[k * 256 + tid] = W[k * 256 + tid];
#pragma unroll
    for (int k = 0; k < 16; k++) {
        int idx = k * 256 + tid;
        int rl = idx >> 7, f = idx & 127;
        int row = row0 + rl;
        int n = row & (N_SZ - 1);
        xs[idx] = x[(size_t)row * F_SZ + f] * (1.0f + nw[n]) + nb[n];
    }
    if (tid < 128) {
        a1s[tid] = a[tid];
        a2s[tid] = a[128 + tid];
        gs[tid]  = gamma[tid];
        bs[tid]  = beta[tid];
    }
    __syncthreads();

    const int w = tid >> 5, lane = tid & 31;
    const int rbase = w * 4;

    float acc[4][4];
#pragma unroll
    for (int r = 0; r < 4; r++)
#pragma unroll
        for (int k = 0; k < 4; k++) acc[r][k] = 0.0f;

#pragma unroll 2
    for (int f = 0; f < 128; f++) {
        float w0 = Ws[f * 128 + lane];
        float w1 = Ws[f * 128 + 32 + lane];
        float w2 = Ws[f * 128 + 64 + lane];
        float w3 = Ws[f * 128 + 96 + lane];
#pragma unroll
        for (int r = 0; r < 4; r++) {
            float xv = xs[(rbase + r) * 128 + f];
            acc[r][0] += xv * w0;
            acc[r][1] += xv * w1;
            acc[r][2] += xv * w2;
            acc[r][3] += xv * w3;
        }
    }

#pragma unroll
    for (int r = 0; r < 4; r++) {
        int row = row0 + rbase + r;
        float s = acc[r][0] + acc[r][1] + acc[r][2] + acc[r][3];
#pragma unroll
        for (int o = 16; o; o >>= 1) s += __shfl_xor_sync(0xffffffffu, s, o);
        float mu = s * 0.0078125f;
        float d0 = acc[r][0] - mu, d1 = acc[r][1] - mu;
        float d2 = acc[r][2] - mu, d3 = acc[r][3] - mu;
        float v = d0 * d0 + d1 * d1 + d2 * d2 + d3 * d3;
#pragma unroll
        for (int o = 16; o; o >>= 1) v += __shfl_xor_sync(0xffffffffu, v, o);
        float rstd = rsqrtf(v * 0.0078125f + LN_EPS);
        float h0 = d0 * rstd * gs[lane]      + bs[lane];
        float h1 = d1 * rstd * gs[32 + lane] + bs[32 + lane];
        float h2 = d2 * rstd * gs[64 + lane] + bs[64 + lane];
        float h3 = d3 * rstd * gs[96 + lane] + bs[96 + lane];
        float s1p = h0 * a1s[lane] + h1 * a1s[32 + lane] + h2 * a1s[64 + lane] + h3 * a1s[96 + lane];
        float s2p = h0 * a2s[lane] + h1 * a2s[32 + lane] + h2 * a2s[64 + lane] + h3 * a2s[96 + lane];
#pragma unroll
        for (int o = 16; o; o >>= 1) {
            s1p += __shfl_xor_sync(0xffffffffu, s1p, o);
            s2p += __shfl_xor_sync(0xffffffffu, s2p, o);
        }
        size_t ro = (size_t)row * F_SZ;
        g_h[ro + lane]      = h0;
        g_h[ro + 32 + lane] = h1;
        g_h[ro + 64 + lane] = h2;
        g_h[ro + 96 + lane] = h3;
        g_hb[ro + lane]      = __float2bfloat16(h0);
        g_hb[ro + 32 + lane] = __float2bfloat16(h1);
        g_hb[ro + 64 + lane] = __float2bfloat16(h2);
        g_hb[ro + 96 + lane] = __float2bfloat16(h3);
        if (lane == 0) { g_s1[row] = s1p; g_s2[row] = s2p; }
    }
}

// ---------------------------------------------------------------------------
// Kernel 2: attention via bf16 mma.m16n8k16 + ldmatrix, double-buffered
// cp.async H staging, bitmask adj, no online softmax (scores bounded).
// CTA: 64 i-rows x 128 f, 256 thr (8 warps: warp w -> i-block (w&1)*32,
// f-block (w>>2... (w>>1)*32). SMEM: Hs[2][128][136]bf16 + Ps[64][136]bf16.
// ---------------------------------------------------------------------------
__global__ void __launch_bounds__(256, 2) attn_kernel(float* __restrict__ out)
{
    extern __shared__ char smc[];
    // Hs buffers: 128 rows * 136 bf16 (272 B row stride) each
    const unsigned HS_BYTES = 128 * 272;         // 34816
    __nv_bfloat16* HsGen = (__nv_bfloat16*)smc;  // generic ptr base
    unsigned* Ps32 = (unsigned*)(smc + 2 * HS_BYTES);        // 64 * 68 words
    float*    l_s  = (float*)(smc + 2 * HS_BYTES + 64 * 272);

    const unsigned smemBase = (unsigned)__cvta_generic_to_shared(smc);
    const unsigned psBase   = smemBase + 2 * HS_BYTES;

    const int tid  = threadIdx.x;
    const int w    = tid >> 5;
    const int lane = tid & 31;
    const int b    = blockIdx.y;
    const int i0   = blockIdx.x * 64;

    // pass-1 identity
    const int G = tid >> 2, q = tid & 3;
    const float s1v = g_s1[b * N_SZ + i0 + G];
    const uint4* bits4 = (const uint4*)g_adjbits + (size_t)(i0 + G) * 16;
    const float* s2b = g_s2 + b * N_SZ;

    // mma identity
    const int ib = (w & 1) * 32;
    const int fb = (w >> 1) * 32;

    const __nv_bfloat16* hbb = g_hb + (size_t)b * N_SZ * F_SZ;
    const float*         hbf = g_h  + (size_t)b * N_SZ * F_SZ;

    // ldmatrix lane addresses (byte offsets within buffers)
    // A (Ps): row = ib + ig*16 + (lane&15); col byte = (lane>>4)*16 (+k0*2)
    const unsigned aOff0 = psBase + (unsigned)(ib + (lane & 15)) * 272 + (unsigned)(lane >> 4) * 16;
    const unsigned aOff1 = aOff0 + 16 * 272;
    // B (Hs): k-row = (lane&15) (+k0); n = fb + pair*16 + (lane>>4)*8
    const unsigned bRow = (unsigned)(lane & 15) * 272;
    const unsigned bCol0 = (unsigned)(fb + ((lane >> 4) * 8)) * 2;
    const unsigned bCol1 = bCol0 + 32;   // +16 cols * 2B

    float acc[2][4][4];
#pragma unroll
    for (int ig = 0; ig < 2; ig++)
#pragma unroll
        for (int n = 0; n < 4; n++)
#pragma unroll
            for (int r = 0; r < 4; r++) acc[ig][n][r] = 0.0f;
    float lacc = 0.0f;

    // ---- prologue: stage tile 0 into buf 0 ----
    {
        const char* src = (const char*)(hbb);
#pragma unroll
        for (int kk = 0; kk < 8; kk++) {
            int idx = kk * 256 + tid;
            int row = idx >> 4, c16 = idx & 15;
            unsigned dst = smemBase + (unsigned)row * 272 + (unsigned)c16 * 16;
            asm volatile("cp.async.cg.shared.global [%0], [%1], 16;\n"
                         :: "r"(dst), "l"(src + row * 256 + c16 * 16));
        }
        asm volatile("cp.async.commit_group;\n");
    }

    for (int T = 0; T < 16; T++) {
        const int jt = T * 128;

        // ---- issue stage of next tile into other buffer ----
        if (T < 15) {
            const char* src = (const char*)(hbb + (size_t)(jt + 128) * F_SZ);
            unsigned dbase = smemBase + (unsigned)(((T + 1) & 1)) * HS_BYTES;
#pragma unroll
            for (int kk = 0; kk < 8; kk++) {
                int idx = kk * 256 + tid;
                int row = idx >> 4, c16 = idx & 15;
                unsigned dst = dbase + (unsigned)row * 272 + (unsigned)c16 * 16;
                asm volatile("cp.async.cg.shared.global [%0], [%1], 16;\n"
                             :: "r"(dst), "l"(src + row * 256 + c16 * 16));
            }
            asm volatile("cp.async.commit_group;\n");
        }

        // ---- pass 1: p = bit ? exp(lrelu(s1+s2)) : 0, packed bf16x2 ----
        {
            uint4 m = bits4[T];
            unsigned mw[4] = {m.x, m.y, m.z, m.w};
            unsigned* psrow = Ps32 + G * 68;
#pragma unroll
            for (int w4 = 0; w4 < 4; w4++) {
                unsigned mm = mw[w4];
#pragma unroll
                for (int u = 0; u < 4; u++) {
                    int jj = w4 * 4 + u;
                    int j0 = 8 * jj + 2 * q;
                    float2 s2v = *(const float2*)(s2b + jt + j0);
                    float e0 = s1v + s2v.x, e1 = s1v + s2v.y;
                    float t0 = e0 > 0.f ? e0 : ALPHA * e0;
                    float t1 = e1 > 0.f ? e1 : ALPHA * e1;
                    unsigned bits = (mm >> (8 * u + 2 * q)) & 3u;
                    float p0 = (bits & 1u) ? __expf(t0) : 0.0f;
                    float p1 = (bits & 2u) ? __expf(t1) : 0.0f;
                    __nv_bfloat162 pp = __floats2bfloat162_rn(p0, p1);
                    psrow[4 * jj + q] = *(unsigned*)&pp;
                    float2 pf = __bfloat1622float2(pp);
                    lacc += pf.x + pf.y;
                }
            }
        }

        // ---- wait staging of current tile, make Ps visible ----
        if (T < 15) asm volatile("cp.async.wait_group 1;\n");
        else        asm volatile("cp.async.wait_group 0;\n");
        __syncthreads();

        // ---- mma: ACC += P[64x128] @ H[128x128] ----
        const unsigned hsB = smemBase + (unsigned)(T & 1) * HS_BYTES;
#pragma unroll
        for (int k = 0; k < 8; k++) {      // k0 = k*16
            unsigned a0[2][4];
            {
                unsigned addr = aOff0 + k * 32;
                asm volatile("ldmatrix.sync.aligned.m8n8.x4.shared.b16 {%0,%1,%2,%3}, [%4];"
                             : "=r"(a0[0][0]), "=r"(a0[0][1]), "=r"(a0[0][2]), "=r"(a0[0][3])
                             : "r"(addr));
                addr = aOff1 + k * 32;
                asm volatile("ldmatrix.sync.aligned.m8n8.x4.shared.b16 {%0,%1,%2,%3}, [%4];"
                             : "=r"(a0[1][0]), "=r"(a0[1][1]), "=r"(a0[1][2]), "=r"(a0[1][3])
                             : "r"(addr));
            }
            unsigned bb[2][4];
            {
                unsigned addr = hsB + bRow + (unsigned)k * 16 * 272 + bCol0;
                asm volatile("ldmatrix.sync.aligned.m8n8.x4.trans.shared.b16 {%0,%1,%2,%3}, [%4];"
                             : "=r"(bb[0][0]), "=r"(bb[0][1]), "=r"(bb[0][2]), "=r"(bb[0][3])
                             : "r"(addr));
                addr = hsB + bRow + (unsigned)k * 16 * 272 + bCol1;
                asm volatile("ldmatrix.sync.aligned.m8n8.x4.trans.shared.b16 {%0,%1,%2,%3}, [%4];"
                             : "=r"(bb[1][0]), "=r"(bb[1][1]), "=r"(bb[1][2]), "=r"(bb[1][3])
                             : "r"(addr));
            }
#pragma unroll
            for (int ig = 0; ig < 2; ig++) {
#pragma unroll
                for (int n = 0; n < 4; n++) {
                    // ntile n: pair = n>>1, half = n&1 -> regs bb[pair][2*half..]
                    asm volatile(
                        "mma.sync.aligned.m16n8k16.row.col.f32.bf16.bf16.f32 "
                        "{%0,%1,%2,%3}, {%4,%5,%6,%7}, {%8,%9}, {%0,%1,%2,%3};"
                        : "+f"(acc[ig][n][0]), "+f"(acc[ig][n][1]),
                          "+f"(acc[ig][n][2]), "+f"(acc[ig][n][3])
                        : "r"(a0[ig][0]), "r"(a0[ig][1]), "r"(a0[ig][2]), "r"(a0[ig][3]),
                          "r"(bb[n >> 1][2 * (n & 1)]), "r"(bb[n >> 1][2 * (n & 1) + 1]));
                }
            }
        }
        __syncthreads();   // mma done reading Ps/Hs before overwrite
    }

    // ---- row sums ----
    lacc += __shfl_xor_sync(0xffffffffu, lacc, 1);
    lacc += __shfl_xor_sync(0xffffffffu, lacc, 2);
    if (q == 0) l_s[G] = lacc;
    __syncthreads();

    // ---- epilogue: normalize, +residual, elu ----
#pragma unroll
    for (int ig = 0; ig < 2; ig++) {
#pragma unroll
        for (int rp = 0; rp < 2; rp++) {
            int rl = ib + ig * 16 + (lane >> 2) + 8 * rp;
            float invl = 1.0f / l_s[rl];
            int i = i0 + rl;
#pragma unroll
            for (int n = 0; n < 4; n++) {
                int col = fb + n * 8 + (lane & 3) * 2;
                const float2 r = *(const float2*)(hbf + (size_t)i * F_SZ + col);
                float ox = acc[ig][n][2 * rp]     * invl + r.x;
                float oy = acc[ig][n][2 * rp + 1] * invl + r.y;
                ox = ox > 0.0f ? ox : __expf(ox) - 1.0f;
                oy = oy > 0.0f ? oy : __expf(oy) - 1.0f;
                *(float2*)(out + ((size_t)b * N_SZ + i) * F_SZ + col) = make_float2(ox, oy);
            }
        }
    }
}

// ---------------------------------------------------------------------------
extern "C" void kernel_launch(void* const* d_in, const int* in_sizes, int n_in,
                              void* d_out, int out_size)
{
    const float* x     = (const float*)d_in[0];
    const int*   adj   = (const int*)d_in[1];
    const float* W     = (const float*)d_in[2];
    const float* a     = (const float*)d_in[3];
    const float* nw    = (const float*)d_in[4];
    const float* nb    = (const float*)d_in[5];
    const float* gamma = (const float*)d_in[6];
    const float* beta  = (const float*)d_in[7];
    float* out = (float*)d_out;

    const int prep_smem = (16384 + 4096 + 4 * 128) * 4;        // 83968 B
    const int attn_smem = 2 * 34816 + 64 * 272 + 256;          // 87296 B
    cudaFuncSetAttribute(prep_kernel, cudaFuncAttributeMaxDynamicSharedMemorySize, prep_smem);
    cudaFuncSetAttribute(attn_kernel, cudaFuncAttributeMaxDynamicSharedMemorySize, attn_smem);

    pack_kernel<<<(N_SZ * N_SZ) / 256, 256>>>(adj);
    prep_kernel<<<ROWS_TOTAL / 32, 256, prep_smem>>>(x, W, a, nw, nb, gamma, beta);

    dim3 grid(N_SZ / 64, B_SZ);
    attn_kernel<<<grid, 256, attn_smem>>>(out);
}

// round 7
// speedup vs baseline: 7.3391x; 1.0653x over previous
#include <cuda_runtime.h>
#include <cuda_bf16.h>
#include <math.h>

#define B_SZ 8
#define N_SZ 2048
#define F_SZ 128
#define ROWS_TOTAL (B_SZ * N_SZ)
#define ALPHA 0.2f
#define LN_EPS 1e-5f

// Scratch (__device__ globals: allocation-free rule)
__device__ float          g_h [ROWS_TOTAL * F_SZ];   // post-LN h fp32 (residual)
__device__ __nv_bfloat16  g_hb[ROWS_TOTAL * F_SZ];   // post-LN h bf16 (mma B operand)
__device__ float4         g_rc[ROWS_TOTAL];          // {exp(s1), exp(a*s1), exp(-s1), 0}
__device__ float2         g_e2[ROWS_TOTAL];          // {exp(s2), exp(a*s2)}
__device__ unsigned       g_adjbits[N_SZ * (N_SZ / 32)];

// ---------------------------------------------------------------------------
// Kernel 1: blocks [0,512): prep (scale+GEMM+LN+score factors, h fp32+bf16).
//           blocks [512,1024): pack adj -> bitmask (32 vals/thread).
// ---------------------------------------------------------------------------
__global__ void __launch_bounds__(256) prep_kernel(
    const float* __restrict__ x, const int* __restrict__ adj,
    const float* __restrict__ W, const float* __restrict__ a,
    const float* __restrict__ nw, const float* __restrict__ nb,
    const float* __restrict__ gamma, const float* __restrict__ beta)
{
    const int tid = threadIdx.x;
    if (blockIdx.x >= 512) {
        int gid = (blockIdx.x - 512) * 256 + tid;
        const int4* src = (const int4*)adj + (size_t)gid * 8;
        unsigned bits = 0;
#pragma unroll
        for (int u = 0; u < 8; u++) {
            int4 v = src[u];
            bits |= (v.x > 0 ? 1u : 0u) << (4 * u);
            bits |= (v.y > 0 ? 1u : 0u) << (4 * u + 1);
            bits |= (v.z > 0 ? 1u : 0u) << (4 * u + 2);
            bits |= (v.w > 0 ? 1u : 0u) << (4 * u + 3);
        }
        g_adjbits[gid] = bits;
        return;
    }

    extern __shared__ float sm[];
    float* Ws  = sm;               // 16384
    float* xs  = sm + 16384;       // 4096
    float* a1s = xs + 4096;        // 128
    float* a2s = a1s + 128;        // 128
    float* gs  = a2s + 128;        // 128
    float* bs  = gs + 128;         // 128

    const int row0 = blockIdx.x * 32;

#pragma unroll
    for (int k = 0; k < 64; k++) Ws[k * 256 + tid] = W[k * 256 + tid];
#pragma unroll
    for (int k = 0; k < 16; k++) {
        int idx = k * 256 + tid;
        int rl = idx >> 7, f = idx & 127;
        int row = row0 + rl;
        int n = row & (N_SZ - 1);
        xs[idx] = x[(size_t)row * F_SZ + f] * (1.0f + nw[n]) + nb[n];
    }
    if (tid < 128) {
        a1s[tid] = a[tid];
        a2s[tid] = a[128 + tid];
        gs[tid]  = gamma[tid];
        bs[tid]  = beta[tid];
    }
    __syncthreads();

    const int w = tid >> 5, lane = tid & 31;
    const int rbase = w * 4;
    float acc[4][4];
#pragma unroll
    for (int r = 0; r < 4; r++)
#pragma unroll
        for (int k = 0; k < 4; k++) acc[r][k] = 0.0f;

#pragma unroll 2
    for (int f = 0; f < 128; f++) {
        float w0 = Ws[f * 128 + lane];
        float w1 = Ws[f * 128 + 32 + lane];
        float w2 = Ws[f * 128 + 64 + lane];
        float w3 = Ws[f * 128 + 96 + lane];
#pragma unroll
        for (int r = 0; r < 4; r++) {
            float xv = xs[(rbase + r) * 128 + f];
            acc[r][0] += xv * w0;
            acc[r][1] += xv * w1;
            acc[r][2] += xv * w2;
            acc[r][3] += xv * w3;
        }
    }

#pragma unroll
    for (int r = 0; r < 4; r++) {
        int row = row0 + rbase + r;
        float s = acc[r][0] + acc[r][1] + acc[r][2] + acc[r][3];
#pragma unroll
        for (int o = 16; o; o >>= 1) s += __shfl_xor_sync(0xffffffffu, s, o);
        float mu = s * 0.0078125f;
        float d0 = acc[r][0] - mu, d1 = acc[r][1] - mu;
        float d2 = acc[r][2] - mu, d3 = acc[r][3] - mu;
        float v = d0 * d0 + d1 * d1 + d2 * d2 + d3 * d3;
#pragma unroll
        for (int o = 16; o; o >>= 1) v += __shfl_xor_sync(0xffffffffu, v, o);
        float rstd = rsqrtf(v * 0.0078125f + LN_EPS);
        float h0 = d0 * rstd * gs[lane]      + bs[lane];
        float h1 = d1 * rstd * gs[32 + lane] + bs[32 + lane];
        float h2 = d2 * rstd * gs[64 + lane] + bs[64 + lane];
        float h3 = d3 * rstd * gs[96 + lane] + bs[96 + lane];
        float s1p = h0 * a1s[lane] + h1 * a1s[32 + lane] + h2 * a1s[64 + lane] + h3 * a1s[96 + lane];
        float s2p = h0 * a2s[lane] + h1 * a2s[32 + lane] + h2 * a2s[64 + lane] + h3 * a2s[96 + lane];
#pragma unroll
        for (int o = 16; o; o >>= 1) {
            s1p += __shfl_xor_sync(0xffffffffu, s1p, o);
            s2p += __shfl_xor_sync(0xffffffffu, s2p, o);
        }
        size_t ro = (size_t)row * F_SZ;
        g_h[ro + lane]      = h0;
        g_h[ro + 32 + lane] = h1;
        g_h[ro + 64 + lane] = h2;
        g_h[ro + 96 + lane] = h3;
        g_hb[ro + lane]      = __float2bfloat16(h0);
        g_hb[ro + 32 + lane] = __float2bfloat16(h1);
        g_hb[ro + 64 + lane] = __float2bfloat16(h2);
        g_hb[ro + 96 + lane] = __float2bfloat16(h3);
        if (lane == 0) {
            g_rc[row] = make_float4(__expf(s1p), __expf(ALPHA * s1p), __expf(-s1p), 0.0f);
            g_e2[row] = make_float2(__expf(s2p), __expf(ALPHA * s2p));
        }
    }
}

// ---------------------------------------------------------------------------
// Kernel 2: attention via bf16 mma.m16n8k16 + ldmatrix.
// CTA = 128 i-rows x 128 f, 256 thr (8 warps: ib2=(w&1)*64 -> 4 m16 i-groups,
// fb=(w>>1)*32 -> 4 n8 tiles). Grid 16x8 = 128 CTAs, 1/SM.
// No exp in inner loop: p = mask ? (E2>invE1 ? E1*E2 : F1*F2) : 0.
// SMEM: Hs[2][128][136]bf16 (69632) + Ps[128][136]bf16 (34816)
//       + e2f2[2][64]float4 (2048) + l_s[128]f32 (512) = 107008 B.
// ---------------------------------------------------------------------------
__global__ void __launch_bounds__(256) attn_kernel(float* __restrict__ out)
{
    extern __shared__ char smc[];
    const unsigned HS_BYTES = 128 * 272;                 // 34816 per buffer
    const unsigned PS_OFF   = 2 * HS_BYTES;              // 69632
    const unsigned E2_OFF   = PS_OFF + 34816;            // 104448 (2 x 1024)
    const unsigned LS_OFF   = E2_OFF + 2048;             // 106496

    unsigned* Ps32 = (unsigned*)(smc + PS_OFF);
    float*    l_s  = (float*)(smc + LS_OFF);

    const unsigned smemBase = (unsigned)__cvta_generic_to_shared(smc);
    const unsigned psBase   = smemBase + PS_OFF;

    const int tid  = threadIdx.x;
    const int w    = tid >> 5;
    const int lane = tid & 31;
    const int b    = blockIdx.y;
    const int i0   = blockIdx.x * 128;
    const int bN   = b * N_SZ;

    // ---- pass-1 identity: thread owns rows G and G+64, quad lane q ----
    const int G = tid >> 2, q = tid & 3;
    const float4 rcA = g_rc[bN + i0 + G];
    const float4 rcB = g_rc[bN + i0 + G + 64];
    const uint4* bitsA = (const uint4*)g_adjbits + (size_t)(i0 + G) * 16;
    const uint4* bitsB = (const uint4*)g_adjbits + (size_t)(i0 + G + 64) * 16;

    // ---- mma identity ----
    const int ib2 = (w & 1) * 64;
    const int fb  = (w >> 1) * 32;

    const __nv_bfloat16* hbb = g_hb + (size_t)bN * F_SZ;
    const float*         hbf = g_h  + (size_t)bN * F_SZ;

    // ldmatrix addresses
    unsigned aOff[4];
#pragma unroll
    for (int ig = 0; ig < 4; ig++)
        aOff[ig] = psBase + (unsigned)(ib2 + ig * 16 + (lane & 15)) * 272
                 + (unsigned)(lane >> 4) * 16;
    const unsigned bRow  = (unsigned)(lane & 15) * 272;
    const unsigned bCol0 = (unsigned)(fb + (lane >> 4) * 8) * 2;
    const unsigned bCol1 = bCol0 + 32;

    float acc[4][4][4];
#pragma unroll
    for (int ig = 0; ig < 4; ig++)
#pragma unroll
        for (int n = 0; n < 4; n++)
#pragma unroll
            for (int r = 0; r < 4; r++) acc[ig][n][r] = 0.0f;
    float laccA = 0.0f, laccB = 0.0f;

    // ---- staging helper (tile T into buffer buf) ----
    auto stage = [&](int T, int buf) {
        const char* src = (const char*)(hbb + (size_t)T * 128 * F_SZ);
        unsigned dbase = smemBase + (unsigned)buf * HS_BYTES;
#pragma unroll
        for (int kk = 0; kk < 8; kk++) {
            int idx = kk * 256 + tid;
            int row = idx >> 4, c16 = idx & 15;
            unsigned dst = dbase + (unsigned)row * 272 + (unsigned)c16 * 16;
            asm volatile("cp.async.cg.shared.global [%0], [%1], 16;"
                         :: "r"(dst), "l"(src + row * 256 + c16 * 16));
        }
        if (tid < 64) {
            unsigned dst = smemBase + E2_OFF + (unsigned)buf * 1024 + (unsigned)tid * 16;
            const char* esrc = (const char*)(g_e2 + bN + T * 128 + 2 * tid);
            asm volatile("cp.async.cg.shared.global [%0], [%1], 16;"
                         :: "r"(dst), "l"(esrc));
        }
        asm volatile("cp.async.commit_group;");
    };

    stage(0, 0);

    for (int T = 0; T < 16; T++) {
        asm volatile("cp.async.wait_group 0;");
        __syncthreads();   // staged tile T (Hs, e2f2) visible everywhere

        // ---- pass 1: scores for rows G, G+64; j = 8u+2q, 8u+2q+1 ----
        {
            const float4* e2p = (const float4*)(smc + E2_OFF + (T & 1) * 1024);
            uint4 mA = bitsA[T], mB = bitsB[T];
            unsigned mwA[4] = {mA.x, mA.y, mA.z, mA.w};
            unsigned mwB[4] = {mB.x, mB.y, mB.z, mB.w};
            unsigned* rowA = Ps32 + G * 68;
            unsigned* rowB = rowA + 64 * 68;
#pragma unroll
            for (int u = 0; u < 16; u++) {
                float4 ef = e2p[4 * u + q];            // {E2a,F2a,E2b,F2b}
                unsigned sh = 8u * (u & 3) + 2u * (unsigned)q;
                unsigned bA = (mwA[u >> 2] >> sh) & 3u;
                unsigned bB = (mwB[u >> 2] >> sh) & 3u;

                float pa = (ef.x > rcA.z) ? rcA.x * ef.x : rcA.y * ef.y;
                float pb = (ef.z > rcA.z) ? rcA.x * ef.z : rcA.y * ef.w;
                pa = (bA & 1u) ? pa : 0.0f;
                pb = (bA & 2u) ? pb : 0.0f;
                __nv_bfloat162 qa = __floats2bfloat162_rn(pa, pb);
                rowA[4 * u + q] = *(unsigned*)&qa;
                float2 fa = __bfloat1622float2(qa);
                laccA += fa.x + fa.y;

                float pc = (ef.x > rcB.z) ? rcB.x * ef.x : rcB.y * ef.y;
                float pd = (ef.z > rcB.z) ? rcB.x * ef.z : rcB.y * ef.w;
                pc = (bB & 1u) ? pc : 0.0f;
                pd = (bB & 2u) ? pd : 0.0f;
                __nv_bfloat162 qb = __floats2bfloat162_rn(pc, pd);
                rowB[4 * u + q] = *(unsigned*)&qb;
                float2 fbv = __bfloat1622float2(qb);
                laccB += fbv.x + fbv.y;
            }
        }
        __syncthreads();   // Ps visible; prior mma reads of Hs[(T+1)&1] long done

        if (T < 15) stage(T + 1, (T + 1) & 1);

        // ---- mma: ACC[128x128] += P @ H ----
        const unsigned hsB = smemBase + (unsigned)(T & 1) * HS_BYTES;
#pragma unroll
        for (int k = 0; k < 8; k++) {
            unsigned af[4][4];
#pragma unroll
            for (int ig = 0; ig < 4; ig++) {
                unsigned addr = aOff[ig] + (unsigned)k * 32;
                asm volatile("ldmatrix.sync.aligned.m8n8.x4.shared.b16 {%0,%1,%2,%3}, [%4];"
                             : "=r"(af[ig][0]), "=r"(af[ig][1]), "=r"(af[ig][2]), "=r"(af[ig][3])
                             : "r"(addr));
            }
            unsigned bb[2][4];
            {
                unsigned addr = hsB + bRow + (unsigned)k * 16 * 272 + bCol0;
                asm volatile("ldmatrix.sync.aligned.m8n8.x4.trans.shared.b16 {%0,%1,%2,%3}, [%4];"
                             : "=r"(bb[0][0]), "=r"(bb[0][1]), "=r"(bb[0][2]), "=r"(bb[0][3])
                             : "r"(addr));
                addr = hsB + bRow + (unsigned)k * 16 * 272 + bCol1;
                asm volatile("ldmatrix.sync.aligned.m8n8.x4.trans.shared.b16 {%0,%1,%2,%3}, [%4];"
                             : "=r"(bb[1][0]), "=r"(bb[1][1]), "=r"(bb[1][2]), "=r"(bb[1][3])
                             : "r"(addr));
            }
#pragma unroll
            for (int ig = 0; ig < 4; ig++) {
#pragma unroll
                for (int n = 0; n < 4; n++) {
                    asm volatile(
                        "mma.sync.aligned.m16n8k16.row.col.f32.bf16.bf16.f32 "
                        "{%0,%1,%2,%3}, {%4,%5,%6,%7}, {%8,%9}, {%0,%1,%2,%3};"
                        : "+f"(acc[ig][n][0]), "+f"(acc[ig][n][1]),
                          "+f"(acc[ig][n][2]), "+f"(acc[ig][n][3])
                        : "r"(af[ig][0]), "r"(af[ig][1]), "r"(af[ig][2]), "r"(af[ig][3]),
                          "r"(bb[n >> 1][2 * (n & 1)]), "r"(bb[n >> 1][2 * (n & 1) + 1]));
                }
            }
        }
    }

    // ---- row sums ----
    laccA += __shfl_xor_sync(0xffffffffu, laccA, 1);
    laccA += __shfl_xor_sync(0xffffffffu, laccA, 2);
    laccB += __shfl_xor_sync(0xffffffffu, laccB, 1);
    laccB += __shfl_xor_sync(0xffffffffu, laccB, 2);
    if (q == 0) { l_s[G] = laccA; l_s[G + 64] = laccB; }
    __syncthreads();

    // ---- epilogue: normalize, +residual, elu ----
#pragma unroll
    for (int ig = 0; ig < 4; ig++) {
#pragma unroll
        for (int rp = 0; rp < 2; rp++) {
            int rl = ib2 + ig * 16 + (lane >> 2) + 8 * rp;
            float invl = 1.0f / l_s[rl];
            int i = i0 + rl;
#pragma unroll
            for (int n = 0; n < 4; n++) {
                int col = fb + n * 8 + (lane & 3) * 2;
                const float2 r = *(const float2*)(hbf + (size_t)i * F_SZ + col);
                float ox = acc[ig][n][2 * rp]     * invl + r.x;
                float oy = acc[ig][n][2 * rp + 1] * invl + r.y;
                ox = ox > 0.0f ? ox : __expf(ox) - 1.0f;
                oy = oy > 0.0f ? oy : __expf(oy) - 1.0f;
                *(float2*)(out + ((size_t)bN + i) * F_SZ + col) = make_float2(ox, oy);
            }
        }
    }
}

// ---------------------------------------------------------------------------
extern "C" void kernel_launch(void* const* d_in, const int* in_sizes, int n_in,
                              void* d_out, int out_size)
{
    const float* x     = (const float*)d_in[0];
    const int*   adj   = (const int*)d_in[1];
    const float* W     = (const float*)d_in[2];
    const float* a     = (const float*)d_in[3];
    const float* nw    = (const float*)d_in[4];
    const float* nb    = (const float*)d_in[5];
    const float* gamma = (const float*)d_in[6];
    const float* beta  = (const float*)d_in[7];
    float* out = (float*)d_out;

    const int prep_smem = (16384 + 4096 + 4 * 128) * 4;       // 83968 B
    const int attn_smem = 107008;
    cudaFuncSetAttribute(prep_kernel, cudaFuncAttributeMaxDynamicSharedMemorySize, prep_smem);
    cudaFuncSetAttribute(attn_kernel, cudaFuncAttributeMaxDynamicSharedMemorySize, attn_smem);

    prep_kernel<<<1024, 256, prep_smem>>>(x, adj, W, a, nw, nb, gamma, beta);

    dim3 grid(N_SZ / 128, B_SZ);
    attn_kernel<<<grid, 256, attn_smem>>>(out);
}

// round 8
// speedup vs baseline: 7.7090x; 1.0504x over previous
#include <cuda_runtime.h>
#include <cuda_bf16.h>
#include <math.h>

#define B_SZ 8
#define N_SZ 2048
#define F_SZ 128
#define ROWS_TOTAL (B_SZ * N_SZ)
#define ALPHA 0.2f
#define LN_EPS 1e-5f

// Scratch (__device__ globals: allocation-free rule)
__device__ float          g_h [ROWS_TOTAL * F_SZ];   // post-LN h fp32 (residual)
__device__ __nv_bfloat16  g_hb[ROWS_TOTAL * F_SZ];   // post-LN h bf16 (mma B operand)
__device__ float4         g_rc[ROWS_TOTAL];          // {exp(s1), exp(a*s1), exp(-s1), 0}
__device__ float2         g_e2[ROWS_TOTAL];          // {exp(s2), exp(a*s2)}
__device__ unsigned       g_adjbits[N_SZ * (N_SZ / 32)];

// ---------------------------------------------------------------------------
// Kernel 1: blocks [0,512): prep (scale+GEMM+LN+score factors, h fp32+bf16).
//           blocks [512,1024): pack adj -> bitmask (32 vals/thread).
// ---------------------------------------------------------------------------
__global__ void __launch_bounds__(256) prep_kernel(
    const float* __restrict__ x, const int* __restrict__ adj,
    const float* __restrict__ W, const float* __restrict__ a,
    const float* __restrict__ nw, const float* __restrict__ nb,
    const float* __restrict__ gamma, const float* __restrict__ beta)
{
    const int tid = threadIdx.x;
    if (blockIdx.x >= 512) {
        int gid = (blockIdx.x - 512) * 256 + tid;
        const int4* src = (const int4*)adj + (size_t)gid * 8;
        unsigned bits = 0;
#pragma unroll
        for (int u = 0; u < 8; u++) {
            int4 v = src[u];
            bits |= (v.x > 0 ? 1u : 0u) << (4 * u);
            bits |= (v.y > 0 ? 1u : 0u) << (4 * u + 1);
            bits |= (v.z > 0 ? 1u : 0u) << (4 * u + 2);
            bits |= (v.w > 0 ? 1u : 0u) << (4 * u + 3);
        }
        g_adjbits[gid] = bits;
        return;
    }

    extern __shared__ float sm[];
    float* Ws  = sm;               // 16384
    float* xs  = sm + 16384;       // 4096
    float* a1s = xs + 4096;        // 128
    float* a2s = a1s + 128;        // 128
    float* gs  = a2s + 128;        // 128
    float* bs  = gs + 128;         // 128

    const int row0 = blockIdx.x * 32;

#pragma unroll
    for (int k = 0; k < 64; k++) Ws[k * 256 + tid] = W[k * 256 + tid];
#pragma unroll
    for (int k = 0; k < 16; k++) {
        int idx = k * 256 + tid;
        int rl = idx >> 7, f = idx & 127;
        int row = row0 + rl;
        int n = row & (N_SZ - 1);
        xs[idx] = x[(size_t)row * F_SZ + f] * (1.0f + nw[n]) + nb[n];
    }
    if (tid < 128) {
        a1s[tid] = a[tid];
        a2s[tid] = a[128 + tid];
        gs[tid]  = gamma[tid];
        bs[tid]  = beta[tid];
    }
    __syncthreads();

    const int w = tid >> 5, lane = tid & 31;
    const int rbase = w * 4;
    float acc[4][4];
#pragma unroll
    for (int r = 0; r < 4; r++)
#pragma unroll
        for (int k = 0; k < 4; k++) acc[r][k] = 0.0f;

#pragma unroll 2
    for (int f = 0; f < 128; f++) {
        float w0 = Ws[f * 128 + lane];
        float w1 = Ws[f * 128 + 32 + lane];
        float w2 = Ws[f * 128 + 64 + lane];
        float w3 = Ws[f * 128 + 96 + lane];
#pragma unroll
        for (int r = 0; r < 4; r++) {
            float xv = xs[(rbase + r) * 128 + f];
            acc[r][0] += xv * w0;
            acc[r][1] += xv * w1;
            acc[r][2] += xv * w2;
            acc[r][3] += xv * w3;
        }
    }

#pragma unroll
    for (int r = 0; r < 4; r++) {
        int row = row0 + rbase + r;
        float s = acc[r][0] + acc[r][1] + acc[r][2] + acc[r][3];
#pragma unroll
        for (int o = 16; o; o >>= 1) s += __shfl_xor_sync(0xffffffffu, s, o);
        float mu = s * 0.0078125f;
        float d0 = acc[r][0] - mu, d1 = acc[r][1] - mu;
        float d2 = acc[r][2] - mu, d3 = acc[r][3] - mu;
        float v = d0 * d0 + d1 * d1 + d2 * d2 + d3 * d3;
#pragma unroll
        for (int o = 16; o; o >>= 1) v += __shfl_xor_sync(0xffffffffu, v, o);
        float rstd = rsqrtf(v * 0.0078125f + LN_EPS);
        float h0 = d0 * rstd * gs[lane]      + bs[lane];
        float h1 = d1 * rstd * gs[32 + lane] + bs[32 + lane];
        float h2 = d2 * rstd * gs[64 + lane] + bs[64 + lane];
        float h3 = d3 * rstd * gs[96 + lane] + bs[96 + lane];
        float s1p = h0 * a1s[lane] + h1 * a1s[32 + lane] + h2 * a1s[64 + lane] + h3 * a1s[96 + lane];
        float s2p = h0 * a2s[lane] + h1 * a2s[32 + lane] + h2 * a2s[64 + lane] + h3 * a2s[96 + lane];
#pragma unroll
        for (int o = 16; o; o >>= 1) {
            s1p += __shfl_xor_sync(0xffffffffu, s1p, o);
            s2p += __shfl_xor_sync(0xffffffffu, s2p, o);
        }
        size_t ro = (size_t)row * F_SZ;
        g_h[ro + lane]      = h0;
        g_h[ro + 32 + lane] = h1;
        g_h[ro + 64 + lane] = h2;
        g_h[ro + 96 + lane] = h3;
        g_hb[ro + lane]      = __float2bfloat16(h0);
        g_hb[ro + 32 + lane] = __float2bfloat16(h1);
        g_hb[ro + 64 + lane] = __float2bfloat16(h2);
        g_hb[ro + 96 + lane] = __float2bfloat16(h3);
        if (lane == 0) {
            g_rc[row] = make_float4(__expf(s1p), __expf(ALPHA * s1p), __expf(-s1p), 0.0f);
            g_e2[row] = make_float2(__expf(s2p), __expf(ALPHA * s2p));
        }
    }
}

// ---------------------------------------------------------------------------
// Kernel 2: attention via bf16 mma.m16n8k16 + ldmatrix, 512 threads (16 warps)
// per 128x128 CTA tile, double-buffered Hs AND Ps -> ONE barrier per tile.
// Warp w: ib2=(w&3)*32 (2 m16 i-groups), fb=(w>>2)*32 (4 n8 tiles).
// Pass-1: thread owns row G=tid>>2, quad lane q. Grid 16x8 = 128 CTAs, 1/SM.
// SMEM: Hs[2][128][272B] (69632) + Ps[2][128][272B] (69632)
//       + e2f2[2][1024B] + l_s[128] = 141824 B.
// ---------------------------------------------------------------------------
__global__ void __launch_bounds__(512) attn_kernel(float* __restrict__ out)
{
    extern __shared__ char smc[];
    const unsigned HS_BYTES = 128 * 272;                 // 34816
    const unsigned PS_OFF   = 2 * HS_BYTES;              // 69632
    const unsigned E2_OFF   = PS_OFF + 2 * HS_BYTES;     // 139264
    const unsigned LS_OFF   = E2_OFF + 2048;             // 141312

    unsigned* Ps32 = (unsigned*)(smc + PS_OFF);
    float*    l_s  = (float*)(smc + LS_OFF);

    const unsigned smemBase = (unsigned)__cvta_generic_to_shared(smc);
    const unsigned psBase   = smemBase + PS_OFF;

    const int tid  = threadIdx.x;
    const int w    = tid >> 5;
    const int lane = tid & 31;
    const int b    = blockIdx.y;
    const int i0   = blockIdx.x * 128;
    const int bN   = b * N_SZ;

    // ---- pass-1 identity: thread owns row G, quad lane q ----
    const int G = tid >> 2, q = tid & 3;
    const float4 rcA = g_rc[bN + i0 + G];
    const uint4* bitsA = (const uint4*)g_adjbits + (size_t)(i0 + G) * 16;

    // ---- mma identity ----
    const int ib2 = (w & 3) * 32;
    const int fb  = (w >> 2) * 32;

    const __nv_bfloat16* hbb = g_hb + (size_t)bN * F_SZ;
    const float*         hbf = g_h  + (size_t)bN * F_SZ;

    // ldmatrix addresses (Ps buffer offset added per tile)
    unsigned aOff[2];
#pragma unroll
    for (int ig = 0; ig < 2; ig++)
        aOff[ig] = psBase + (unsigned)(ib2 + ig * 16 + (lane & 15)) * 272
                 + (unsigned)(lane >> 4) * 16;
    const unsigned bRow  = (unsigned)(lane & 15) * 272;
    const unsigned bCol0 = (unsigned)(fb + (lane >> 4) * 8) * 2;
    const unsigned bCol1 = bCol0 + 32;

    float acc[2][4][4];
#pragma unroll
    for (int ig = 0; ig < 2; ig++)
#pragma unroll
        for (int n = 0; n < 4; n++)
#pragma unroll
            for (int r = 0; r < 4; r++) acc[ig][n][r] = 0.0f;
    float lacc = 0.0f;

    // ---- staging: tile T into Hs[buf] + e2f2[buf] ----
    auto stage = [&](int T, int buf) {
        const char* src = (const char*)(hbb + (size_t)T * 128 * F_SZ);
        unsigned dbase = smemBase + (unsigned)buf * HS_BYTES;
#pragma unroll
        for (int kk = 0; kk < 4; kk++) {
            int idx = kk * 512 + tid;
            int row = idx >> 4, c16 = idx & 15;
            unsigned dst = dbase + (unsigned)row * 272 + (unsigned)c16 * 16;
            asm volatile("cp.async.cg.shared.global [%0], [%1], 16;"
                         :: "r"(dst), "l"(src + row * 256 + c16 * 16));
        }
        if (tid < 64) {
            unsigned dst = smemBase + E2_OFF + (unsigned)buf * 1024 + (unsigned)tid * 16;
            const char* esrc = (const char*)(g_e2 + bN + T * 128 + 2 * tid);
            asm volatile("cp.async.cg.shared.global [%0], [%1], 16;"
                         :: "r"(dst), "l"(esrc));
        }
        asm volatile("cp.async.commit_group;");
    };

    stage(0, 0);

    for (int T = 0; T < 16; T++) {
        const int buf = T & 1;

        // ---- pass 1 into Ps[buf]: j = 8u+2q, 8u+2q+1 ----
        {
            // e2f2 of tile T was staged with Hs(T); wait own copies first.
            asm volatile("cp.async.wait_group 0;");
            const float4* e2p = (const float4*)(smc + E2_OFF + buf * 1024);
            uint4 mA = bitsA[T];
            unsigned mwA[4] = {mA.x, mA.y, mA.z, mA.w};
            unsigned* rowA = Ps32 + buf * 8704 + G * 68;
#pragma unroll
            for (int u = 0; u < 16; u++) {
                float4 ef = e2p[4 * u + q];            // {E2a,F2a,E2b,F2b}
                unsigned sh = 8u * (u & 3) + 2u * (unsigned)q;
                unsigned bA = (mwA[u >> 2] >> sh) & 3u;
                float pa = (ef.x > rcA.z) ? rcA.x * ef.x : rcA.y * ef.y;
                float pb = (ef.z > rcA.z) ? rcA.x * ef.z : rcA.y * ef.w;
                pa = (bA & 1u) ? pa : 0.0f;
                pb = (bA & 2u) ? pb : 0.0f;
                __nv_bfloat162 qa = __floats2bfloat162_rn(pa, pb);
                rowA[4 * u + q] = *(unsigned*)&qa;
                float2 fa = __bfloat1622float2(qa);
                lacc += fa.x + fa.y;
            }
        }
        __syncthreads();   // Ps(T) + all warps' Hs(T) staging visible

        if (T < 15) stage(T + 1, buf ^ 1);

        // ---- mma: ACC[128x128] += P @ H ----
        const unsigned hsB  = smemBase + (unsigned)buf * HS_BYTES;
        const unsigned psB  = (unsigned)buf * HS_BYTES;
#pragma unroll
        for (int k = 0; k < 8; k++) {
            unsigned af[2][4];
#pragma unroll
            for (int ig = 0; ig < 2; ig++) {
                unsigned addr = aOff[ig] + psB + (unsigned)k * 32;
                asm volatile("ldmatrix.sync.aligned.m8n8.x4.shared.b16 {%0,%1,%2,%3}, [%4];"
                             : "=r"(af[ig][0]), "=r"(af[ig][1]), "=r"(af[ig][2]), "=r"(af[ig][3])
                             : "r"(addr));
            }
            unsigned bb[2][4];
            {
                unsigned addr = hsB + bRow + (unsigned)k * 16 * 272 + bCol0;
                asm volatile("ldmatrix.sync.aligned.m8n8.x4.trans.shared.b16 {%0,%1,%2,%3}, [%4];"
                             : "=r"(bb[0][0]), "=r"(bb[0][1]), "=r"(bb[0][2]), "=r"(bb[0][3])
                             : "r"(addr));
                addr = hsB + bRow + (unsigned)k * 16 * 272 + bCol1;
                asm volatile("ldmatrix.sync.aligned.m8n8.x4.trans.shared.b16 {%0,%1,%2,%3}, [%4];"
                             : "=r"(bb[1][0]), "=r"(bb[1][1]), "=r"(bb[1][2]), "=r"(bb[1][3])
                             : "r"(addr));
            }
#pragma unroll
            for (int ig = 0; ig < 2; ig++) {
#pragma unroll
                for (int n = 0; n < 4; n++) {
                    asm volatile(
                        "mma.sync.aligned.m16n8k16.row.col.f32.bf16.bf16.f32 "
                        "{%0,%1,%2,%3}, {%4,%5,%6,%7}, {%8,%9}, {%0,%1,%2,%3};"
                        : "+f"(acc[ig][n][0]), "+f"(acc[ig][n][1]),
                          "+f"(acc[ig][n][2]), "+f"(acc[ig][n][3])
                        : "r"(af[ig][0]), "r"(af[ig][1]), "r"(af[ig][2]), "r"(af[ig][3]),
                          "r"(bb[n >> 1][2 * (n & 1)]), "r"(bb[n >> 1][2 * (n & 1) + 1]));
                }
            }
        }
    }

    // ---- row sums ----
    lacc += __shfl_xor_sync(0xffffffffu, lacc, 1);
    lacc += __shfl_xor_sync(0xffffffffu, lacc, 2);
    if (q == 0) l_s[G] = lacc;
    __syncthreads();

    // ---- epilogue: normalize, +residual, elu ----
#pragma unroll
    for (int ig = 0; ig < 2; ig++) {
#pragma unroll
        for (int rp = 0; rp < 2; rp++) {
            int rl = ib2 + ig * 16 + (lane >> 2) + 8 * rp;
            float invl = 1.0f / l_s[rl];
            int i = i0 + rl;
#pragma unroll
            for (int n = 0; n < 4; n++) {
                int col = fb + n * 8 + (lane & 3) * 2;
                const float2 r = *(const float2*)(hbf + (size_t)i * F_SZ + col);
                float ox = acc[ig][n][2 * rp]     * invl + r.x;
                float oy = acc[ig][n][2 * rp + 1] * invl + r.y;
                ox = ox > 0.0f ? ox : __expf(ox) - 1.0f;
                oy = oy > 0.0f ? oy : __expf(oy) - 1.0f;
                *(float2*)(out + ((size_t)bN + i) * F_SZ + col) = make_float2(ox, oy);
            }
        }
    }
}

// ---------------------------------------------------------------------------
extern "C" void kernel_launch(void* const* d_in, const int* in_sizes, int n_in,
                              void* d_out, int out_size)
{
    const float* x     = (const float*)d_in[0];
    const int*   adj   = (const int*)d_in[1];
    const float* W     = (const float*)d_in[2];
    const float* a     = (const float*)d_in[3];
    const float* nw    = (const float*)d_in[4];
    const float* nb    = (const float*)d_in[5];
    const float* gamma = (const float*)d_in[6];
    const float* beta  = (const float*)d_in[7];
    float* out = (float*)d_out;

    const int prep_smem = (16384 + 4096 + 4 * 128) * 4;       // 83968 B
    const int attn_smem = 141824;
    cudaFuncSetAttribute(prep_kernel, cudaFuncAttributeMaxDynamicSharedMemorySize, prep_smem);
    cudaFuncSetAttribute(attn_kernel, cudaFuncAttributeMaxDynamicSharedMemorySize, attn_smem);

    prep_kernel<<<1024, 256, prep_smem>>>(x, adj, W, a, nw, nb, gamma, beta);

    dim3 grid(N_SZ / 128, B_SZ);
    attn_kernel<<<grid, 512, attn_smem>>>(out);
}